// round 11
// baseline (speedup 1.0000x reference)
#include <cuda_runtime.h>

#define HID   64
#define RS    8
#define KIH   24
#define WIDTH 24
#define L0R   8
#define R0R   24
#define OW    16
#define WB    8          // batches per warp (warp fully owns them)
#define NWARP 4
#define NTHR  128
#define CTAB  32
#define NKP   44         // k-pairs (88 k)
#define RBW   24

// smem float offsets
#define OFF_W    0
#define W_FLOATS (NKP*4*32*4)                // 22528
#define OFF_BIAS (OFF_W + W_FLOATS)          // 22528
#define OFF_WL   (OFF_BIAS + 256)            // 22784
#define OFF_BL   (OFF_WL + 192)              // 22976
#define OFF_HX   (OFF_BL + 4)                // 22980 (x4 -> 16B aligned)
#define HXBUF    (NWARP*WB*HID)              // 2048 per buffer
#define OFF_RBQ  (OFF_HX + 2*HXBUF)          // 27076
#define RBQ_FLOATS (NWARP*WB*3*RBW*4)        // 9216
#define SMEM_FLOATS (OFF_RBQ + RBQ_FLOATS)   // 36292 -> ~145 KB

typedef unsigned long long u64;

union F4U { float4 f4; struct { u64 lo, hi; } u; };

static __device__ __forceinline__ u64 pack2(float a, float b){
  u64 r; asm("mov.b64 %0, {%1, %2};" : "=l"(r) : "f"(a), "f"(b)); return r;
}
static __device__ __forceinline__ void unpack2(u64 v, float& a, float& b){
  asm("mov.b64 {%0, %1}, %2;" : "=f"(a), "=f"(b) : "l"(v));
}
static __device__ __forceinline__ u64 ffma2(u64 a, u64 b, u64 c){
  u64 d; asm("fma.rn.f32x2 %0, %1, %2, %3;" : "=l"(d) : "l"(a), "l"(b), "l"(c));
  return d;
}
static __device__ __forceinline__ float tanha(float x){
  float y; asm("tanh.approx.f32 %0, %1;" : "=f"(y) : "f"(x)); return y;
}
static __device__ __forceinline__ float sigf(float x){
  return fmaf(tanha(0.5f*x), 0.5f, 0.5f);
}

__global__ void __launch_bounds__(NTHR, 1)
pixelrnn_kernel(const float* __restrict__ x,
                const float* __restrict__ W_ih,
                const float* __restrict__ W_hh,
                const float* __restrict__ b_ih,
                const float* __restrict__ b_hh,
                const float* __restrict__ Wl,
                const float* __restrict__ bl,
                float* __restrict__ out)
{
  extern __shared__ float sm[];
  const int tid  = threadIdx.x;
  const int warp = tid >> 5, lane = tid & 31;

  // ---- stage weights ----
  // W4[(kp*4 + t)*32 + ln] = ( w(k0,rA), w(k0,rB), w(k1,rA), w(k1,rB) )
  //   k0 = 2kp, k1 = 2kp+1; rA = t*64 + ln, rB = rA + 32 (gate rows i,f,g,o)
  //   k < 24 -> W_ih col k; else W_hh col k-24
  //   u.lo = k0 pair (hidA,hidB); u.hi = k1 pair
  {
    float4* W4 = (float4*)(sm + OFF_W);
    for (int i = tid; i < NKP*4*32; i += NTHR){
      int ln = i & 31, t = (i >> 5) & 3, kp = i >> 7;
      int rA = t*64 + ln, rB = rA + 32;
      int k0 = 2*kp;
      float4 v;
      if (k0 < KIH){
        v = make_float4(W_ih[rA*KIH + k0],     W_ih[rB*KIH + k0],
                        W_ih[rA*KIH + k0 + 1], W_ih[rB*KIH + k0 + 1]);
      } else {
        int kk = k0 - KIH;
        v = make_float4(W_hh[rA*HID + kk],     W_hh[rB*HID + kk],
                        W_hh[rA*HID + kk + 1], W_hh[rB*HID + kk + 1]);
      }
      W4[i] = v;
    }
  }
  for (int i = tid; i < 256; i += NTHR) sm[OFF_BIAS + i] = b_ih[i] + b_hh[i];
  for (int i = tid; i < 3*HID; i += NTHR) sm[OFF_WL + i] = Wl[i];
  if (tid < 3) sm[OFF_BL + tid] = bl[tid];
  for (int i = tid; i < 2*HXBUF; i += NTHR) sm[OFF_HX + i] = 0.f;
  __syncthreads();

  const int bbase = blockIdx.x * CTAB + warp * WB;
  float* hxb0 = sm + OFF_HX + warp * (WB*HID);
  float* hxb1 = hxb0 + HXBUF;
  float4* rbq = (float4*)(sm + OFF_RBQ) + warp * (WB*3*RBW);
  float*  rbf = (float*)rbq;
  const float4* wq  = (const float4*)(sm + OFF_W) + lane;
  const float4* wlq = (const float4*)(sm + OFF_WL);

  // biases packed (hidA, hidB) per gate type
  u64 bj[4];
#pragma unroll
  for (int t = 0; t < 4; t++)
    bj[t] = pack2(sm[OFF_BIAS + t*64 + lane], sm[OFF_BIAS + t*64 + lane + 32]);

  float cx0[WB], cx1[WB];
#pragma unroll
  for (int b = 0; b < WB; b++){ cx0[b] = 0.f; cx1[b] = 0.f; }

  const int  vb = lane / 3, vch = lane - 3*vb;     // lanes 0..23 own (vb,vch)
  const bool vact = (lane < 24);
  const float blv = vact ? sm[OFF_BL + vch] : 0.f;
  float* outp = vact ? out + ((size_t)(bbase + vb)*3 + vch)*(OW*OW) : out;

  int ph = 0, sctr = 0;

  for (int r = L0R; r < R0R; r++){
    // init slots 0..7 from x (cols >= 8 get v-patched before any read)
    for (int i = lane; i < WB*3*8; i += 32){
      int b = i / 24;
      int rem = i - b*24;
      int ch = rem >> 3, s = rem & 7;
      const float* xr = x + (size_t)(bbase + b)*(3*WIDTH*WIDTH)
                          + ch*(WIDTH*WIDTH) + r*WIDTH + s;
      rbq[(b*3 + ch)*RBW + s] = make_float4(xr[0], xr[1], xr[2], xr[3]);
    }
    __syncwarp();

    for (int c = RS; c < WIDTH; c++){
      float* hxr = ph ? hxb1 : hxb0;   // h(t-1)
      float* hxw = ph ? hxb0 : hxb1;   // h(t)
      const float4* hxq = (const float4*)hxr;

      // acc[b][t] = (partial for hidA=lane, hidB=lane+32) of gate-type t
      u64 acc[WB][4];
#pragma unroll
      for (int b = 0; b < WB; b++)
#pragma unroll
        for (int t = 0; t < 4; t++) acc[b][t] = bj[t];

      // ---- input feed: 6 quads (iq -> ch=iq>>1, 4 k each, kp = 2iq, 2iq+1) ----
#pragma unroll
      for (int iq = 0; iq < 6; iq++){
        F4U wA0, wA1, wA2, wA3, wB0, wB1, wB2, wB3;
        wA0.f4 = wq[((2*iq+0)*4 + 0)*32];
        wA1.f4 = wq[((2*iq+0)*4 + 1)*32];
        wA2.f4 = wq[((2*iq+0)*4 + 2)*32];
        wA3.f4 = wq[((2*iq+0)*4 + 3)*32];
        wB0.f4 = wq[((2*iq+1)*4 + 0)*32];
        wB1.f4 = wq[((2*iq+1)*4 + 1)*32];
        wB2.f4 = wq[((2*iq+1)*4 + 2)*32];
        wB3.f4 = wq[((2*iq+1)*4 + 3)*32];
        int ch = iq >> 1;
        int base = c - RS + 4*(iq & 1);
#pragma unroll
        for (int b = 0; b < WB; b++){
          float4 a = rbq[(b*3 + ch)*RBW + base];
          u64 sx = pack2(a.x, a.x), sy = pack2(a.y, a.y);
          u64 sz = pack2(a.z, a.z), sw = pack2(a.w, a.w);
          acc[b][0] = ffma2(sx, wA0.u.lo, acc[b][0]);
          acc[b][1] = ffma2(sx, wA1.u.lo, acc[b][1]);
          acc[b][2] = ffma2(sx, wA2.u.lo, acc[b][2]);
          acc[b][3] = ffma2(sx, wA3.u.lo, acc[b][3]);
          acc[b][0] = ffma2(sy, wA0.u.hi, acc[b][0]);
          acc[b][1] = ffma2(sy, wA1.u.hi, acc[b][1]);
          acc[b][2] = ffma2(sy, wA2.u.hi, acc[b][2]);
          acc[b][3] = ffma2(sy, wA3.u.hi, acc[b][3]);
          acc[b][0] = ffma2(sz, wB0.u.lo, acc[b][0]);
          acc[b][1] = ffma2(sz, wB1.u.lo, acc[b][1]);
          acc[b][2] = ffma2(sz, wB2.u.lo, acc[b][2]);
          acc[b][3] = ffma2(sz, wB3.u.lo, acc[b][3]);
          acc[b][0] = ffma2(sw, wB0.u.hi, acc[b][0]);
          acc[b][1] = ffma2(sw, wB1.u.hi, acc[b][1]);
          acc[b][2] = ffma2(sw, wB2.u.hi, acc[b][2]);
          acc[b][3] = ffma2(sw, wB3.u.hi, acc[b][3]);
        }
      }

      // ---- hidden feed: 16 quads (jq -> kp = 12+2jq, 13+2jq) ----
#pragma unroll 4
      for (int jq = 0; jq < 16; jq++){
        F4U wA0, wA1, wA2, wA3, wB0, wB1, wB2, wB3;
        wA0.f4 = wq[((12 + 2*jq)*4 + 0)*32];
        wA1.f4 = wq[((12 + 2*jq)*4 + 1)*32];
        wA2.f4 = wq[((12 + 2*jq)*4 + 2)*32];
        wA3.f4 = wq[((12 + 2*jq)*4 + 3)*32];
        wB0.f4 = wq[((13 + 2*jq)*4 + 0)*32];
        wB1.f4 = wq[((13 + 2*jq)*4 + 1)*32];
        wB2.f4 = wq[((13 + 2*jq)*4 + 2)*32];
        wB3.f4 = wq[((13 + 2*jq)*4 + 3)*32];
#pragma unroll
        for (int b = 0; b < WB; b++){
          float4 a = hxq[b*16 + jq];
          u64 sx = pack2(a.x, a.x), sy = pack2(a.y, a.y);
          u64 sz = pack2(a.z, a.z), sw = pack2(a.w, a.w);
          acc[b][0] = ffma2(sx, wA0.u.lo, acc[b][0]);
          acc[b][1] = ffma2(sx, wA1.u.lo, acc[b][1]);
          acc[b][2] = ffma2(sx, wA2.u.lo, acc[b][2]);
          acc[b][3] = ffma2(sx, wA3.u.lo, acc[b][3]);
          acc[b][0] = ffma2(sy, wA0.u.hi, acc[b][0]);
          acc[b][1] = ffma2(sy, wA1.u.hi, acc[b][1]);
          acc[b][2] = ffma2(sy, wA2.u.hi, acc[b][2]);
          acc[b][3] = ffma2(sy, wA3.u.hi, acc[b][3]);
          acc[b][0] = ffma2(sz, wB0.u.lo, acc[b][0]);
          acc[b][1] = ffma2(sz, wB1.u.lo, acc[b][1]);
          acc[b][2] = ffma2(sz, wB2.u.lo, acc[b][2]);
          acc[b][3] = ffma2(sz, wB3.u.lo, acc[b][3]);
          acc[b][0] = ffma2(sw, wB0.u.hi, acc[b][0]);
          acc[b][1] = ffma2(sw, wB1.u.hi, acc[b][1]);
          acc[b][2] = ffma2(sw, wB2.u.hi, acc[b][2]);
          acc[b][3] = ffma2(sw, wB3.u.hi, acc[b][3]);
        }
      }

      // ---- lane-local cell update (gates already fully summed per half) ----
#pragma unroll
      for (int b = 0; b < WB; b++){
        float giA, giB, gfA, gfB, ggA, ggB, goA, goB;
        unpack2(acc[b][0], giA, giB);
        unpack2(acc[b][1], gfA, gfB);
        unpack2(acc[b][2], ggA, ggB);
        unpack2(acc[b][3], goA, goB);
        float c0 = sigf(gfA)*cx0[b] + sigf(giA)*tanha(ggA);
        float c1 = sigf(gfB)*cx1[b] + sigf(giB)*tanha(ggB);
        cx0[b] = c0; cx1[b] = c1;
        hxw[b*HID + lane]      = sigf(goA)*tanha(c0);
        hxw[b*HID + lane + 32] = sigf(goB)*tanha(c1);
      }
      __syncwarp();

      // ---- head v (lanes 0..23: batch vb, channel vch) ----
      if (vact){
        const float4* hq = (const float4*)hxw;
        u64 va = pack2(0.f, 0.f);
#pragma unroll
        for (int j = 0; j < 16; j++){
          F4U a; a.f4 = hq[vb*16 + j];
          F4U w; w.f4 = wlq[vch*16 + j];
          va = ffma2(a.u.lo, w.u.lo, va);
          va = ffma2(a.u.hi, w.u.hi, va);
        }
        float v0, v1; unpack2(va, v0, v1);
        float v = v0 + v1 + blv;
        v = fmaxf(v, 0.01f*v);
#pragma unroll
        for (int t = 0; t < 4; t++)
          rbf[((vb*3 + vch)*RBW + (c - t))*4 + t] = v;
        outp[sctr] = v;
      }
      __syncwarp();
      ph ^= 1;
      sctr++;
    }
  }
}

extern "C" void kernel_launch(void* const* d_in, const int* in_sizes, int n_in,
                              void* d_out, int out_size)
{
  const float* x    = (const float*)d_in[0];
  const float* W_ih = (const float*)d_in[1];
  const float* W_hh = (const float*)d_in[2];
  const float* b_ih = (const float*)d_in[3];
  const float* b_hh = (const float*)d_in[4];
  const float* Wl   = (const float*)d_in[5];
  const float* bl   = (const float*)d_in[6];

  int B = in_sizes[0] / (3*WIDTH*WIDTH);
  int grid = B / CTAB;   // 4096/32 = 128 CTAs

  size_t smem = SMEM_FLOATS * sizeof(float);   // ~145 KB
  cudaFuncSetAttribute(pixelrnn_kernel,
                       cudaFuncAttributeMaxDynamicSharedMemorySize, (int)smem);

  pixelrnn_kernel<<<grid, NTHR, smem>>>(x, W_ih, W_hh, b_ih, b_hh, Wl, bl,
                                        (float*)d_out);
}

// round 12
// speedup vs baseline: 1.0919x; 1.0919x over previous
#include <cuda_runtime.h>

#define HID   64
#define RS    8
#define KIH   24
#define WIDTH 24
#define L0R   8
#define R0R   24
#define OW    16
#define WB    4          // batches per warp (warp fully owns them)
#define NWARP 8
#define NTHR  256
#define CTAB  32
#define NKP   44         // k-pairs (88 k)
#define RBW   24

// smem float offsets
#define OFF_W    0
#define W_FLOATS (NKP*4*32*4)                // 22528
#define OFF_BIAS (OFF_W + W_FLOATS)          // 22528
#define OFF_WL   (OFF_BIAS + 256)            // 22784
#define OFF_BL   (OFF_WL + 192)              // 22976
#define OFF_HX   (OFF_BL + 4)                // 22980 (x4 -> 16B aligned)
#define HXBUF    (NWARP*WB*HID)              // 2048 per buffer
#define OFF_RBQ  (OFF_HX + 2*HXBUF)          // 27076
#define RBQ_FLOATS (NWARP*WB*3*RBW*4)        // 9216
#define SMEM_FLOATS (OFF_RBQ + RBQ_FLOATS)   // 36292 -> ~145 KB

typedef unsigned long long u64;

union F4U { float4 f4; struct { u64 lo, hi; } u; };

static __device__ __forceinline__ u64 pack2(float a, float b){
  u64 r; asm("mov.b64 %0, {%1, %2};" : "=l"(r) : "f"(a), "f"(b)); return r;
}
static __device__ __forceinline__ void unpack2(u64 v, float& a, float& b){
  asm("mov.b64 {%0, %1}, %2;" : "=f"(a), "=f"(b) : "l"(v));
}
static __device__ __forceinline__ u64 ffma2(u64 a, u64 b, u64 c){
  u64 d; asm("fma.rn.f32x2 %0, %1, %2, %3;" : "=l"(d) : "l"(a), "l"(b), "l"(c));
  return d;
}
static __device__ __forceinline__ float tanha(float x){
  float y; asm("tanh.approx.f32 %0, %1;" : "=f"(y) : "f"(x)); return y;
}
static __device__ __forceinline__ float sigf(float x){
  return fmaf(tanha(0.5f*x), 0.5f, 0.5f);
}

__global__ void __launch_bounds__(NTHR, 1)
pixelrnn_kernel(const float* __restrict__ x,
                const float* __restrict__ W_ih,
                const float* __restrict__ W_hh,
                const float* __restrict__ b_ih,
                const float* __restrict__ b_hh,
                const float* __restrict__ Wl,
                const float* __restrict__ bl,
                float* __restrict__ out)
{
  extern __shared__ float sm[];
  const int tid  = threadIdx.x;
  const int warp = tid >> 5, lane = tid & 31;

  // ---- stage weights (shared by all warps) ----
  // W4[(kp*4 + t)*32 + ln] = ( w(k0,rA), w(k0,rB), w(k1,rA), w(k1,rB) )
  //   k0 = 2kp, k1 = 2kp+1; rA = t*64 + ln, rB = rA + 32 (gate rows i,f,g,o)
  //   k < 24 -> W_ih col k; else W_hh col k-24
  //   u.lo = k0 pair (hidA,hidB); u.hi = k1 pair
  {
    float4* W4 = (float4*)(sm + OFF_W);
    for (int i = tid; i < NKP*4*32; i += NTHR){
      int ln = i & 31, t = (i >> 5) & 3, kp = i >> 7;
      int rA = t*64 + ln, rB = rA + 32;
      int k0 = 2*kp;
      float4 v;
      if (k0 < KIH){
        v = make_float4(W_ih[rA*KIH + k0],     W_ih[rB*KIH + k0],
                        W_ih[rA*KIH + k0 + 1], W_ih[rB*KIH + k0 + 1]);
      } else {
        int kk = k0 - KIH;
        v = make_float4(W_hh[rA*HID + kk],     W_hh[rB*HID + kk],
                        W_hh[rA*HID + kk + 1], W_hh[rB*HID + kk + 1]);
      }
      W4[i] = v;
    }
  }
  for (int i = tid; i < 256; i += NTHR) sm[OFF_BIAS + i] = b_ih[i] + b_hh[i];
  for (int i = tid; i < 3*HID; i += NTHR) sm[OFF_WL + i] = Wl[i];
  if (tid < 3) sm[OFF_BL + tid] = bl[tid];
  for (int i = tid; i < 2*HXBUF; i += NTHR) sm[OFF_HX + i] = 0.f;
  __syncthreads();

  const int bbase = blockIdx.x * CTAB + warp * WB;
  float* hxb0 = sm + OFF_HX + warp * (WB*HID);
  float* hxb1 = hxb0 + HXBUF;
  float4* rbq = (float4*)(sm + OFF_RBQ) + warp * (WB*3*RBW);
  float*  rbf = (float*)rbq;
  const float4* wq  = (const float4*)(sm + OFF_W) + lane;
  const float4* wlq = (const float4*)(sm + OFF_WL);

  // biases packed (hidA, hidB) per gate type
  u64 bj[4];
#pragma unroll
  for (int t = 0; t < 4; t++)
    bj[t] = pack2(sm[OFF_BIAS + t*64 + lane], sm[OFF_BIAS + t*64 + lane + 32]);

  float cx0[WB], cx1[WB];
#pragma unroll
  for (int b = 0; b < WB; b++){ cx0[b] = 0.f; cx1[b] = 0.f; }

  const int  vb = lane / 3, vch = lane - 3*vb;     // lanes 0..11 own (vb,vch)
  const bool vact = (lane < 3*WB);
  const float blv = vact ? sm[OFF_BL + vch] : 0.f;
  float* outp = vact ? out + ((size_t)(bbase + vb)*3 + vch)*(OW*OW) : out;

  int ph = 0, sctr = 0;

  for (int r = L0R; r < R0R; r++){
    // init slots 0..7 from x (cols >= 8 get v-patched before any read)
    for (int i = lane; i < WB*3*8; i += 32){
      int b = i / 24;
      int rem = i - b*24;
      int ch = rem >> 3, s = rem & 7;
      const float* xr = x + (size_t)(bbase + b)*(3*WIDTH*WIDTH)
                          + ch*(WIDTH*WIDTH) + r*WIDTH + s;
      rbq[(b*3 + ch)*RBW + s] = make_float4(xr[0], xr[1], xr[2], xr[3]);
    }
    __syncwarp();

    for (int c = RS; c < WIDTH; c++){
      float* hxr = ph ? hxb1 : hxb0;   // h(t-1)
      float* hxw = ph ? hxb0 : hxb1;   // h(t)
      const float4* hxq = (const float4*)hxr;

      // acc[b][t] = (partial for hidA=lane, hidB=lane+32) of gate-type t
      u64 acc[WB][4];
#pragma unroll
      for (int b = 0; b < WB; b++)
#pragma unroll
        for (int t = 0; t < 4; t++) acc[b][t] = bj[t];

      // ---- input feed: 6 quads (iq -> ch=iq>>1, 4 k each, kp = 2iq, 2iq+1) ----
#pragma unroll
      for (int iq = 0; iq < 6; iq++){
        F4U wA0, wA1, wA2, wA3, wB0, wB1, wB2, wB3;
        wA0.f4 = wq[((2*iq+0)*4 + 0)*32];
        wA1.f4 = wq[((2*iq+0)*4 + 1)*32];
        wA2.f4 = wq[((2*iq+0)*4 + 2)*32];
        wA3.f4 = wq[((2*iq+0)*4 + 3)*32];
        wB0.f4 = wq[((2*iq+1)*4 + 0)*32];
        wB1.f4 = wq[((2*iq+1)*4 + 1)*32];
        wB2.f4 = wq[((2*iq+1)*4 + 2)*32];
        wB3.f4 = wq[((2*iq+1)*4 + 3)*32];
        int ch = iq >> 1;
        int base = c - RS + 4*(iq & 1);
#pragma unroll
        for (int b = 0; b < WB; b++){
          float4 a = rbq[(b*3 + ch)*RBW + base];
          u64 sx = pack2(a.x, a.x), sy = pack2(a.y, a.y);
          u64 sz = pack2(a.z, a.z), sw = pack2(a.w, a.w);
          acc[b][0] = ffma2(sx, wA0.u.lo, acc[b][0]);
          acc[b][1] = ffma2(sx, wA1.u.lo, acc[b][1]);
          acc[b][2] = ffma2(sx, wA2.u.lo, acc[b][2]);
          acc[b][3] = ffma2(sx, wA3.u.lo, acc[b][3]);
          acc[b][0] = ffma2(sy, wA0.u.hi, acc[b][0]);
          acc[b][1] = ffma2(sy, wA1.u.hi, acc[b][1]);
          acc[b][2] = ffma2(sy, wA2.u.hi, acc[b][2]);
          acc[b][3] = ffma2(sy, wA3.u.hi, acc[b][3]);
          acc[b][0] = ffma2(sz, wB0.u.lo, acc[b][0]);
          acc[b][1] = ffma2(sz, wB1.u.lo, acc[b][1]);
          acc[b][2] = ffma2(sz, wB2.u.lo, acc[b][2]);
          acc[b][3] = ffma2(sz, wB3.u.lo, acc[b][3]);
          acc[b][0] = ffma2(sw, wB0.u.hi, acc[b][0]);
          acc[b][1] = ffma2(sw, wB1.u.hi, acc[b][1]);
          acc[b][2] = ffma2(sw, wB2.u.hi, acc[b][2]);
          acc[b][3] = ffma2(sw, wB3.u.hi, acc[b][3]);
        }
      }

      // ---- hidden feed: 16 quads (jq -> kp = 12+2jq, 13+2jq) ----
#pragma unroll 8
      for (int jq = 0; jq < 16; jq++){
        F4U wA0, wA1, wA2, wA3, wB0, wB1, wB2, wB3;
        wA0.f4 = wq[((12 + 2*jq)*4 + 0)*32];
        wA1.f4 = wq[((12 + 2*jq)*4 + 1)*32];
        wA2.f4 = wq[((12 + 2*jq)*4 + 2)*32];
        wA3.f4 = wq[((12 + 2*jq)*4 + 3)*32];
        wB0.f4 = wq[((13 + 2*jq)*4 + 0)*32];
        wB1.f4 = wq[((13 + 2*jq)*4 + 1)*32];
        wB2.f4 = wq[((13 + 2*jq)*4 + 2)*32];
        wB3.f4 = wq[((13 + 2*jq)*4 + 3)*32];
#pragma unroll
        for (int b = 0; b < WB; b++){
          float4 a = hxq[b*16 + jq];
          u64 sx = pack2(a.x, a.x), sy = pack2(a.y, a.y);
          u64 sz = pack2(a.z, a.z), sw = pack2(a.w, a.w);
          acc[b][0] = ffma2(sx, wA0.u.lo, acc[b][0]);
          acc[b][1] = ffma2(sx, wA1.u.lo, acc[b][1]);
          acc[b][2] = ffma2(sx, wA2.u.lo, acc[b][2]);
          acc[b][3] = ffma2(sx, wA3.u.lo, acc[b][3]);
          acc[b][0] = ffma2(sy, wA0.u.hi, acc[b][0]);
          acc[b][1] = ffma2(sy, wA1.u.hi, acc[b][1]);
          acc[b][2] = ffma2(sy, wA2.u.hi, acc[b][2]);
          acc[b][3] = ffma2(sy, wA3.u.hi, acc[b][3]);
          acc[b][0] = ffma2(sz, wB0.u.lo, acc[b][0]);
          acc[b][1] = ffma2(sz, wB1.u.lo, acc[b][1]);
          acc[b][2] = ffma2(sz, wB2.u.lo, acc[b][2]);
          acc[b][3] = ffma2(sz, wB3.u.lo, acc[b][3]);
          acc[b][0] = ffma2(sw, wB0.u.hi, acc[b][0]);
          acc[b][1] = ffma2(sw, wB1.u.hi, acc[b][1]);
          acc[b][2] = ffma2(sw, wB2.u.hi, acc[b][2]);
          acc[b][3] = ffma2(sw, wB3.u.hi, acc[b][3]);
        }
      }

      // ---- lane-local cell update (gates already fully summed per half) ----
#pragma unroll
      for (int b = 0; b < WB; b++){
        float giA, giB, gfA, gfB, ggA, ggB, goA, goB;
        unpack2(acc[b][0], giA, giB);
        unpack2(acc[b][1], gfA, gfB);
        unpack2(acc[b][2], ggA, ggB);
        unpack2(acc[b][3], goA, goB);
        float c0 = sigf(gfA)*cx0[b] + sigf(giA)*tanha(ggA);
        float c1 = sigf(gfB)*cx1[b] + sigf(giB)*tanha(ggB);
        cx0[b] = c0; cx1[b] = c1;
        hxw[b*HID + lane]      = sigf(goA)*tanha(c0);
        hxw[b*HID + lane + 32] = sigf(goB)*tanha(c1);
      }
      __syncwarp();

      // ---- head v (lanes 0..11: batch vb, channel vch) ----
      if (vact){
        const float4* hq = (const float4*)hxw;
        u64 va = pack2(0.f, 0.f);
#pragma unroll
        for (int j = 0; j < 16; j++){
          F4U a; a.f4 = hq[vb*16 + j];
          F4U w; w.f4 = wlq[vch*16 + j];
          va = ffma2(a.u.lo, w.u.lo, va);
          va = ffma2(a.u.hi, w.u.hi, va);
        }
        float v0, v1; unpack2(va, v0, v1);
        float v = v0 + v1 + blv;
        v = fmaxf(v, 0.01f*v);
#pragma unroll
        for (int t = 0; t < 4; t++)
          rbf[((vb*3 + vch)*RBW + (c - t))*4 + t] = v;
        outp[sctr] = v;
      }
      __syncwarp();
      ph ^= 1;
      sctr++;
    }
  }
}

extern "C" void kernel_launch(void* const* d_in, const int* in_sizes, int n_in,
                              void* d_out, int out_size)
{
  const float* x    = (const float*)d_in[0];
  const float* W_ih = (const float*)d_in[1];
  const float* W_hh = (const float*)d_in[2];
  const float* b_ih = (const float*)d_in[3];
  const float* b_hh = (const float*)d_in[4];
  const float* Wl   = (const float*)d_in[5];
  const float* bl   = (const float*)d_in[6];

  int B = in_sizes[0] / (3*WIDTH*WIDTH);
  int grid = B / CTAB;   // 4096/32 = 128 CTAs

  size_t smem = SMEM_FLOATS * sizeof(float);   // ~145 KB
  cudaFuncSetAttribute(pixelrnn_kernel,
                       cudaFuncAttributeMaxDynamicSharedMemorySize, (int)smem);

  pixelrnn_kernel<<<grid, NTHR, smem>>>(x, W_ih, W_hh, b_ih, b_hh, Wl, bl,
                                        (float*)d_out);
}